// round 9
// baseline (speedup 1.0000x reference)
#include <cuda_runtime.h>
#include <cuda_fp16.h>
#include <cstdint>

#define BB    16
#define HH    512
#define WW    512
#define HW    (HH * WW)
#define NPIX  (BB * HW)

#define RSTR  520                       // padded row stride (8-elem gap per row)
#define FPAD  528                       // per-image front pad (>= RSTR+2, mult of 8)
#define BPAD  528                       // per-image back pad
#define IMG   (FPAD + HH * RSTR + BPAD) // 267296 elems per padded image
#define PTOT  (BB * IMG)

typedef unsigned int u32;

// Padded, zero-initialized device globals. Gaps/pads are NEVER written: they
// stay 0.0, so unconditional neighbor reads return exact reference-boundary
// semantics (pred=0 outside image; A value there finite and multiplied by 0).
// Dirs: 0=(0,1) 1=(1,-1) 2=(1,0) 3=(1,1);   A = exp(entry) unnormalized,
// symmetric: A_d(p) == A_{-d}(p+d); center = exp(1); invS = 0.5*weight/S.
__device__ __half g_A[4][PTOT];    // 34.2 MB
__device__ __half g_invS[NPIX];    //  8.4 MB (unpadded; always exact-pixel)
__device__ float  g_buf[2][PTOT];  // padded ping-pong pred buffers, 34.2 MB

#define AC 2.7182818284590452f     // exp(1): center softmax-numerator

__global__ __launch_bounds__(256)
void build_kernel(const float* __restrict__ image,
                  const float* __restrict__ theta,
                  const float* __restrict__ weight)
{
    int idx = blockIdx.x * 256 + threadIdx.x;
    if (idx >= NPIX) return;
    int w = idx & (WW - 1);
    int h = (idx >> 9) & (HH - 1);
    int b = idx >> 18;

    float t0 = theta[0], t1 = theta[1], t2 = theta[2];
    const float* img = image + b * HW;
    float c = img[h * WW + w] * 255.0f;

    float A[9];
#pragma unroll
    for (int k = 0; k < 9; k++) {
        int dx = k / 3 - 1, dy = k % 3 - 1;
        int hh = h + dx, ww = w + dy;
        float e = 0.0f;
        if ((unsigned)hh < HH && (unsigned)ww < WW) {
            float d    = img[hh * WW + ww] * 255.0f - c;
            float dist = t0 * (float)(dx * dx) + t1 * (float)(dy * dy) + t2 * d * d;
            e = __expf(-0.5f * dist);
        }
        A[k] = __expf(e);          // invalid neighbor -> exp(0) = 1
    }

    // Sum S from fp16-ROUNDED values: exactly what the message pass reads
    // (forward at p and backward at p-d are bit-identical by symmetry).
    float S = AC;
#pragma unroll
    for (int k = 0; k < 9; k++)
        if (k != 4) S += __half2float(__float2half(A[k]));

    int pidx = b * IMG + FPAD + h * RSTR + w;
    g_A[0][pidx] = __float2half(A[5]);   // (0, 1)
    g_A[1][pidx] = __float2half(A[6]);   // (1,-1)
    g_A[2][pidx] = __float2half(A[7]);   // (1, 0)
    g_A[3][pidx] = __float2half(A[8]);   // (1, 1)
    g_invS[idx]  = __float2half(0.5f * weight[0] / S);
}

__device__ __forceinline__ float2 h2f(const u32 u) {
    return __half22float2(*reinterpret_cast<const __half2*>(&u));
}
__device__ __forceinline__ void unpack8(const uint4 v, float* f) {
    float2 a = h2f(v.x), b = h2f(v.y), c = h2f(v.z), d = h2f(v.w);
    f[0] = a.x; f[1] = a.y; f[2] = b.x; f[3] = b.y;
    f[4] = c.x; f[5] = c.y; f[6] = d.x; f[7] = d.y;
}

// ---------------------------------------------------------------------------
// One Jacobi iteration, 8 px per thread. Steady state (!FIRST) is fully
// branch-free: padded geometry makes every load unconditional.
// ---------------------------------------------------------------------------
template<bool FIRST>
__global__ __launch_bounds__(256)
void message_pass(const float* __restrict__ pin,
                  const float* __restrict__ unary,
                  float* __restrict__ pout, int last)
{
    int t  = blockIdx.x * 256 + threadIdx.x;         // octet index
    int w8 = (t & 63) << 3;
    int h  = (t >> 6) & (HH - 1);
    int b  = t >> 15;
    int uidx = b * HW + (h << 9) + w8;               // unpadded index
    int pidx = b * IMG + FPAD + h * RSTR + w8;       // padded index
    int up   = pidx - RSTR;

    // ---- A loads: all unconditional (pads make every index in-bounds)
    const __half* P0 = g_A[0]; const __half* P1 = g_A[1];
    const __half* P2 = g_A[2]; const __half* P3 = g_A[3];
    uint4 F0 = __ldg((const uint4*)&P0[pidx]);   // A0[p..p+7]
    uint4 F1 = __ldg((const uint4*)&P1[pidx]);
    uint4 F2 = __ldg((const uint4*)&P2[pidx]);
    uint4 F3 = __ldg((const uint4*)&P3[pidx]);
    u32   B0 = __ldg((const u32*)&P0[pidx - 2]); // .y = A0[p-1]
    uint4 U1 = __ldg((const uint4*)&P1[up]);     // A1[u..u+7]
    u32   E1 = __ldg((const u32*)&P1[up + 8]);   // .x = A1[u+8]
    uint4 U2 = __ldg((const uint4*)&P2[up]);
    uint4 U3 = __ldg((const uint4*)&P3[up]);
    u32   E3 = __ldg((const u32*)&P3[up - 2]);   // .y = A3[u-1]
    uint4 SV = __ldg((const uint4*)&g_invS[uidx]);
    float4 ua = __ldg((const float4*)(unary + uidx));
    float4 ub = __ldg((const float4*)(unary + uidx + 4));

    // ---- pred neighborhood: 3 rows x cols [w8-1 .. w8+8]
    float row[3][10];
#pragma unroll
    for (int r = 0; r < 3; r++) {
        if (FIRST) {
            int gh = h + r - 1;
            if ((unsigned)gh >= HH) {
#pragma unroll
                for (int c = 0; c < 10; c++) row[r][c] = 0.0f;
                continue;
            }
            const float* p = pin + uidx + (r - 1) * WW;
            float4 v0 = *(const float4*)p;
            float4 v1 = *(const float4*)(p + 4);
            row[r][1] = v0.x; row[r][2] = v0.y; row[r][3] = v0.z; row[r][4] = v0.w;
            row[r][5] = v1.x; row[r][6] = v1.y; row[r][7] = v1.z; row[r][8] = v1.w;
            row[r][0] = (w8 > 0)       ? p[-1] : 0.0f;
            row[r][9] = (w8 + 8 < WW)  ? p[8]  : 0.0f;
        } else {
            const float* p = pin + pidx + (r - 1) * RSTR;  // pads/gaps give 0
            float4 v0 = *(const float4*)p;
            float4 v1 = *(const float4*)(p + 4);
            row[r][1] = v0.x; row[r][2] = v0.y; row[r][3] = v0.z; row[r][4] = v0.w;
            row[r][5] = v1.x; row[r][6] = v1.y; row[r][7] = v1.z; row[r][8] = v1.w;
            row[r][0] = p[-1];
            row[r][9] = p[8];
        }
    }

    float acc[8];
#pragma unroll
    for (int j = 0; j < 8; j++) acc[j] = AC * row[1][j + 1];   // center

    {   // dir0 (0,±1): same-row
        float f[8]; unpack8(F0, f);
#pragma unroll
        for (int j = 0; j < 8; j++) acc[j] += f[j] * row[1][j + 2];   // fwd
        acc[0] += h2f(B0).y * row[1][0];                              // bwd edge
#pragma unroll
        for (int j = 1; j < 8; j++) acc[j] += f[j - 1] * row[1][j];   // bwd
    }
    {   // dir1 (+1,-1) fwd / (-1,+1) bwd
        float f[8]; unpack8(F1, f);
#pragma unroll
        for (int j = 0; j < 8; j++) acc[j] += f[j] * row[2][j];
        float u[8]; unpack8(U1, u);
#pragma unroll
        for (int j = 0; j < 7; j++) acc[j] += u[j + 1] * row[0][j + 2];
        acc[7] += h2f(E1).x * row[0][9];
    }
    {   // dir2 (+1,0) fwd / (-1,0) bwd
        float f[8]; unpack8(F2, f);
#pragma unroll
        for (int j = 0; j < 8; j++) acc[j] += f[j] * row[2][j + 1];
        float u[8]; unpack8(U2, u);
#pragma unroll
        for (int j = 0; j < 8; j++) acc[j] += u[j] * row[0][j + 1];
    }
    {   // dir3 (+1,+1) fwd / (-1,-1) bwd
        float f[8]; unpack8(F3, f);
#pragma unroll
        for (int j = 0; j < 8; j++) acc[j] += f[j] * row[2][j + 2];
        float u[8]; unpack8(U3, u);
        acc[0] += h2f(E3).y * row[0][0];
#pragma unroll
        for (int j = 1; j < 8; j++) acc[j] += u[j - 1] * row[0][j];
    }

    float s[8]; unpack8(SV, s);
    float un[8] = {ua.x, ua.y, ua.z, ua.w, ub.x, ub.y, ub.z, ub.w};
    float o[8];
#pragma unroll
    for (int j = 0; j < 8; j++) o[j] = 0.5f * un[j] + s[j] * acc[j];

    float4 o0 = make_float4(o[0], o[1], o[2], o[3]);
    float4 o1 = make_float4(o[4], o[5], o[6], o[7]);
    if (last) {
        *(float4*)(pout + uidx)     = o0;    // final: unpadded d_out
        *(float4*)(pout + uidx + 4) = o1;
    } else {
        *(float4*)(pout + pidx)     = o0;    // padded ping-pong
        *(float4*)(pout + pidx + 4) = o1;
    }
}

extern "C" void kernel_launch(void* const* d_in, const int* in_sizes, int n_in,
                              void* d_out, int out_size)
{
    const float* image  = (const float*)d_in[0];
    const float* unary  = (const float*)d_in[1];
    const float* theta  = (const float*)d_in[2];
    const float* weight = (const float*)d_in[3];
    float* out = (float*)d_out;

    void* baddr = nullptr;
    cudaGetSymbolAddress(&baddr, g_buf);   // non-stream API: capture-safe
    float* buf0 = (float*)baddr;
    float* buf1 = buf0 + PTOT;

    build_kernel<<<NPIX / 256, 256>>>(image, theta, weight);

    const int GRID = (NPIX / 8) / 256;     // 2048 blocks
    message_pass<true><<<GRID, 256>>>(unary, unary, buf0, 0);
    for (int i = 1; i < 10; i++) {
        const float* pin  = ((i - 1) & 1) ? buf1 : buf0;
        float*       pout = (i == 9) ? out : ((i & 1) ? buf1 : buf0);
        message_pass<false><<<GRID, 256>>>(pin, unary, pout, i == 9);
    }
}

// round 10
// speedup vs baseline: 1.0279x; 1.0279x over previous
#include <cuda_runtime.h>
#include <cuda_fp16.h>
#include <cstdint>

#define BB    16
#define HH    512
#define WW    512
#define HW    (HH * WW)
#define NPIX  (BB * HW)

#define RSTR  520                       // padded row stride (8-elem gap per row)
#define FPAD  528                       // per-image front pad
#define BPAD  528                       // per-image back pad
#define IMG   (FPAD + HH * RSTR + BPAD)
#define PTOT  (BB * IMG)

#define SMS   520                       // smem strip row stride (floats)

typedef unsigned int u32;

// Padded, zero-initialized device globals. Gaps/pads are NEVER written: they
// stay 0.0, so unconditional neighbor reads give exact reference-boundary
// semantics (pred=0 outside image; A there finite and multiplied by 0).
// Dirs: 0=(0,1) 1=(1,-1) 2=(1,0) 3=(1,1);  A = exp(entry) unnormalized,
// symmetric: A_d(p) == A_{-d}(p+d); center = exp(1); invS = 0.5*weight/S.
__device__ __half g_A[4][PTOT];    // 34.2 MB
__device__ __half g_invS[NPIX];    //  8.4 MB
__device__ float  g_buf[2][PTOT];  // padded ping-pong pred buffers

#define AC 2.7182818284590452f     // exp(1): center softmax-numerator

__global__ __launch_bounds__(256)
void build_kernel(const float* __restrict__ image,
                  const float* __restrict__ theta,
                  const float* __restrict__ weight)
{
    int idx = blockIdx.x * 256 + threadIdx.x;
    if (idx >= NPIX) return;
    int w = idx & (WW - 1);
    int h = (idx >> 9) & (HH - 1);
    int b = idx >> 18;

    float t0 = theta[0], t1 = theta[1], t2 = theta[2];
    const float* img = image + b * HW;
    float c = img[h * WW + w] * 255.0f;

    float A[9];
#pragma unroll
    for (int k = 0; k < 9; k++) {
        int dx = k / 3 - 1, dy = k % 3 - 1;
        int hh = h + dx, ww = w + dy;
        float e = 0.0f;
        if ((unsigned)hh < HH && (unsigned)ww < WW) {
            float d    = img[hh * WW + ww] * 255.0f - c;
            float dist = t0 * (float)(dx * dx) + t1 * (float)(dy * dy) + t2 * d * d;
            e = __expf(-0.5f * dist);
        }
        A[k] = __expf(e);          // invalid neighbor -> exp(0) = 1
    }

    // Sum S from fp16-ROUNDED values: exactly what the message pass reads.
    float S = AC;
#pragma unroll
    for (int k = 0; k < 9; k++)
        if (k != 4) S += __half2float(__float2half(A[k]));

    int pidx = b * IMG + FPAD + h * RSTR + w;
    g_A[0][pidx] = __float2half(A[5]);   // (0, 1)
    g_A[1][pidx] = __float2half(A[6]);   // (1,-1)
    g_A[2][pidx] = __float2half(A[7]);   // (1, 0)
    g_A[3][pidx] = __float2half(A[8]);   // (1, 1)
    g_invS[idx]  = __float2half(0.5f * weight[0] / S);
}

__device__ __forceinline__ float2 h2f(const u32 u) {
    return __half22float2(*reinterpret_cast<const __half2*>(&u));
}
__device__ __forceinline__ void unpack8(const uint4 v, float* f) {
    float2 a = h2f(v.x), b = h2f(v.y), c = h2f(v.z), d = h2f(v.w);
    f[0] = a.x; f[1] = a.y; f[2] = b.x; f[3] = b.y;
    f[4] = c.x; f[5] = c.y; f[6] = d.x; f[7] = d.y;
}

// ---------------------------------------------------------------------------
// One Jacobi update of 8 px at (b, gh, cols c..c+7). pred read via pc
// (element at (gh, c)) with row stride ps — either padded global (ps=RSTR)
// or an smem strip buffer with zero guards at pc[-1]/pc[8] (ps=SMS).
// A/invS/unary from global (A padded => unconditional).
// ---------------------------------------------------------------------------
__device__ __forceinline__ void jacobi8(
    int b, int gh, int c,
    const float* __restrict__ pc, int ps,
    const float* __restrict__ unary, float* o)
{
    int uidx = b * HW + (gh << 9) + c;
    int pidx = b * IMG + FPAD + gh * RSTR + c;
    int up   = pidx - RSTR;

    const __half* P0 = g_A[0]; const __half* P1 = g_A[1];
    const __half* P2 = g_A[2]; const __half* P3 = g_A[3];
    uint4 F0 = __ldg((const uint4*)&P0[pidx]);
    uint4 F1 = __ldg((const uint4*)&P1[pidx]);
    uint4 F2 = __ldg((const uint4*)&P2[pidx]);
    uint4 F3 = __ldg((const uint4*)&P3[pidx]);
    u32   B0 = __ldg((const u32*)&P0[pidx - 2]);  // .y = A0[p-1]
    uint4 U1 = __ldg((const uint4*)&P1[up]);
    u32   E1 = __ldg((const u32*)&P1[up + 8]);    // .x = A1[u+8]
    uint4 U2 = __ldg((const uint4*)&P2[up]);
    uint4 U3 = __ldg((const uint4*)&P3[up]);
    u32   E3 = __ldg((const u32*)&P3[up - 2]);    // .y = A3[u-1]
    uint4 SV = __ldg((const uint4*)&g_invS[uidx]);
    float4 ua = __ldg((const float4*)(unary + uidx));
    float4 ub = __ldg((const float4*)(unary + uidx + 4));

    float row[3][10];
#pragma unroll
    for (int r = 0; r < 3; r++) {
        const float* p = pc + (r - 1) * ps;
        float4 v0 = *(const float4*)p;
        float4 v1 = *(const float4*)(p + 4);
        row[r][1] = v0.x; row[r][2] = v0.y; row[r][3] = v0.z; row[r][4] = v0.w;
        row[r][5] = v1.x; row[r][6] = v1.y; row[r][7] = v1.z; row[r][8] = v1.w;
        row[r][0] = p[-1];
        row[r][9] = p[8];
    }

    float acc[8];
#pragma unroll
    for (int j = 0; j < 8; j++) acc[j] = AC * row[1][j + 1];

    {   // dir0 (0,±1)
        float f[8]; unpack8(F0, f);
#pragma unroll
        for (int j = 0; j < 8; j++) acc[j] += f[j] * row[1][j + 2];
        acc[0] += h2f(B0).y * row[1][0];
#pragma unroll
        for (int j = 1; j < 8; j++) acc[j] += f[j - 1] * row[1][j];
    }
    {   // dir1 (+1,-1) fwd / (-1,+1) bwd
        float f[8]; unpack8(F1, f);
#pragma unroll
        for (int j = 0; j < 8; j++) acc[j] += f[j] * row[2][j];
        float u[8]; unpack8(U1, u);
#pragma unroll
        for (int j = 0; j < 7; j++) acc[j] += u[j + 1] * row[0][j + 2];
        acc[7] += h2f(E1).x * row[0][9];
    }
    {   // dir2 (+1,0) fwd / (-1,0) bwd
        float f[8]; unpack8(F2, f);
#pragma unroll
        for (int j = 0; j < 8; j++) acc[j] += f[j] * row[2][j + 1];
        float u[8]; unpack8(U2, u);
#pragma unroll
        for (int j = 0; j < 8; j++) acc[j] += u[j] * row[0][j + 1];
    }
    {   // dir3 (+1,+1) fwd / (-1,-1) bwd
        float f[8]; unpack8(F3, f);
#pragma unroll
        for (int j = 0; j < 8; j++) acc[j] += f[j] * row[2][j + 2];
        float u[8]; unpack8(U3, u);
        acc[0] += h2f(E3).y * row[0][0];
#pragma unroll
        for (int j = 1; j < 8; j++) acc[j] += u[j - 1] * row[0][j];
    }

    float s[8]; unpack8(SV, s);
    float un[8] = {ua.x, ua.y, ua.z, ua.w, ub.x, ub.y, ub.z, ub.w};
#pragma unroll
    for (int j = 0; j < 8; j++) o[j] = 0.5f * un[j] + s[j] * acc[j];
}

// ---------------------------------------------------------------------------
// First iteration (pred-in = unary, unpadded): writes padded buf.
// ---------------------------------------------------------------------------
__global__ __launch_bounds__(256)
void first_pass(const float* __restrict__ unary, float* __restrict__ pout)
{
    int t  = blockIdx.x * 256 + threadIdx.x;
    int w8 = (t & 63) << 3;
    int h  = (t >> 6) & (HH - 1);
    int b  = t >> 15;
    int uidx = b * HW + (h << 9) + w8;
    int pidx = b * IMG + FPAD + h * RSTR + w8;

    // pred rows from unary with row checks into a local guarded window
    float win[3][10];
#pragma unroll
    for (int r = 0; r < 3; r++) {
        int gh = h + r - 1;
        if ((unsigned)gh >= HH) {
#pragma unroll
            for (int c = 0; c < 10; c++) win[r][c] = 0.0f;
        } else {
            const float* p = unary + uidx + (r - 1) * WW;
            float4 v0 = *(const float4*)p;
            float4 v1 = *(const float4*)(p + 4);
            win[r][1] = v0.x; win[r][2] = v0.y; win[r][3] = v0.z; win[r][4] = v0.w;
            win[r][5] = v1.x; win[r][6] = v1.y; win[r][7] = v1.z; win[r][8] = v1.w;
            win[r][0] = (w8 > 0)      ? p[-1] : 0.0f;
            win[r][9] = (w8 + 8 < WW) ? p[8]  : 0.0f;
        }
    }
    // reuse jacobi8's A/epilogue by treating win as a tiny strip:
    // simplest: inline the same math via jacobi8 on a stack buffer
    float tmp[30];
#pragma unroll
    for (int r = 0; r < 3; r++)
#pragma unroll
        for (int c = 0; c < 10; c++) tmp[r * 10 + c] = win[r][c];
    float o[8];
    jacobi8(b, h, w8, &tmp[10 + 1], 10, unary, o);
    *(float4*)(pout + pidx)     = make_float4(o[0], o[1], o[2], o[3]);
    *(float4*)(pout + pidx + 4) = make_float4(o[4], o[5], o[6], o[7]);
}

// ---------------------------------------------------------------------------
// Fused 3 Jacobi iterations on a 16-row x 512-col strip.
// bufA: 20 rows (R-2..R+17), bufB: 18 rows (R-1..R+16), stride SMS, with
// zero guards at cols 3 and 516. OOB-image rows stored as 0.
// ---------------------------------------------------------------------------
__global__ __launch_bounds__(512, 2)
void fused3(const float* __restrict__ pin,
            const float* __restrict__ unary,
            float* __restrict__ pout, int last)
{
    extern __shared__ float sm[];
    float* bufA = sm;                  // 20 x SMS
    float* bufB = sm + 20 * SMS;       // 18 x SMS

    int tid = threadIdx.x;
    int blk = blockIdx.x;
    int b   = blk >> 5;
    int R   = (blk & 31) << 4;

    if (tid < 20)      { bufA[tid * SMS + 3] = 0.f; bufA[tid * SMS + 516] = 0.f; }
    else if (tid < 38) { int i = tid - 20;
                         bufB[i * SMS + 3] = 0.f; bufB[i * SMS + 516] = 0.f; }

    // phase 1: rows R-2..R+17 from global pin (padded, branch-free)
    for (int oct = tid; oct < 20 * 64; oct += 512) {
        int i = oct >> 6, c = (oct & 63) << 3;
        int gh = R - 2 + i;
        float* dst = &bufA[i * SMS + 4 + c];
        if ((unsigned)gh < HH) {
            float o[8];
            const float* pc = pin + b * IMG + FPAD + gh * RSTR + c;
            jacobi8(b, gh, c, pc, RSTR, unary, o);
#pragma unroll
            for (int j = 0; j < 8; j++) dst[j] = o[j];
        } else {
#pragma unroll
            for (int j = 0; j < 8; j++) dst[j] = 0.f;
        }
    }
    __syncthreads();

    // phase 2: rows R-1..R+16 from bufA
    for (int oct = tid; oct < 18 * 64; oct += 512) {
        int i = oct >> 6, c = (oct & 63) << 3;
        int gh = R - 1 + i;
        float* dst = &bufB[i * SMS + 4 + c];
        if ((unsigned)gh < HH) {
            float o[8];
            const float* pc = &bufA[(i + 1) * SMS + 4 + c];
            jacobi8(b, gh, c, pc, SMS, unary, o);
#pragma unroll
            for (int j = 0; j < 8; j++) dst[j] = o[j];
        } else {
#pragma unroll
            for (int j = 0; j < 8; j++) dst[j] = 0.f;
        }
    }
    __syncthreads();

    // phase 3: rows R..R+15 from bufB, write global
    for (int oct = tid; oct < 16 * 64; oct += 512) {
        int i = oct >> 6, c = (oct & 63) << 3;
        int gh = R + i;
        float o[8];
        const float* pc = &bufB[(i + 1) * SMS + 4 + c];
        jacobi8(b, gh, c, pc, SMS, unary, o);
        float4 o0 = make_float4(o[0], o[1], o[2], o[3]);
        float4 o1 = make_float4(o[4], o[5], o[6], o[7]);
        if (last) {
            int uidx = b * HW + (gh << 9) + c;
            *(float4*)(pout + uidx)     = o0;
            *(float4*)(pout + uidx + 4) = o1;
        } else {
            int pidx = b * IMG + FPAD + gh * RSTR + c;
            *(float4*)(pout + pidx)     = o0;
            *(float4*)(pout + pidx + 4) = o1;
        }
    }
}

extern "C" void kernel_launch(void* const* d_in, const int* in_sizes, int n_in,
                              void* d_out, int out_size)
{
    const float* image  = (const float*)d_in[0];
    const float* unary  = (const float*)d_in[1];
    const float* theta  = (const float*)d_in[2];
    const float* weight = (const float*)d_in[3];
    float* out = (float*)d_out;

    void* baddr = nullptr;
    cudaGetSymbolAddress(&baddr, g_buf);   // non-stream API: capture-safe
    float* buf0 = (float*)baddr;
    float* buf1 = buf0 + PTOT;

    const int SMEM = (20 + 18) * SMS * (int)sizeof(float);   // 79,040 B
    cudaFuncSetAttribute(fused3, cudaFuncAttributeMaxDynamicSharedMemorySize, SMEM);

    build_kernel<<<NPIX / 256, 256>>>(image, theta, weight);
    first_pass<<<(NPIX / 8) / 256, 256>>>(unary, buf0);          // iter 1
    fused3<<<BB * 32, 512, SMEM>>>(buf0, unary, buf1, 0);        // iters 2-4
    fused3<<<BB * 32, 512, SMEM>>>(buf1, unary, buf0, 0);        // iters 5-7
    fused3<<<BB * 32, 512, SMEM>>>(buf0, unary, out, 1);         // iters 8-10
}

// round 11
// speedup vs baseline: 1.0554x; 1.0268x over previous
#include <cuda_runtime.h>
#include <cuda_fp16.h>
#include <cstdint>

#define BB    16
#define HH    512
#define WW    512
#define HW    (HH * WW)
#define NPIX  (BB * HW)

#define RSTR  520                       // padded row stride
#define FPAD  528                       // per-image front pad
#define BPAD  528                       // per-image back pad
#define IMG   (FPAD + HH * RSTR + BPAD)
#define PTOT  (BB * IMG)

#define SMS   520                       // smem strip row stride (floats)

typedef unsigned int u32;

// Padded, zero-initialized device globals. Gaps/pads are NEVER written: they
// stay 0.0, giving exact reference boundary semantics for unconditional reads.
// Dirs: 0=(0,1) 1=(1,-1) 2=(1,0) 3=(1,1);  A = exp(entry) unnormalized,
// symmetric: A_d(p) == A_{-d}(p+d); center = exp(1); invS = 0.5*weight/S.
__device__ __half g_A[4][PTOT];    // 34.2 MB
__device__ __half g_invS[NPIX];    //  8.4 MB
__device__ float  g_buf[2][PTOT];  // padded ping-pong pred buffers

#define AC 2.7182818284590452f     // exp(1): center softmax-numerator

// ---------------------------------------------------------------------------
// Build pass + iteration 1 fused: computes A planes, invS, AND the first
// Jacobi iteration (pred-in = unary) using the in-register fp32 A values.
// ---------------------------------------------------------------------------
__global__ __launch_bounds__(256)
void build_kernel(const float* __restrict__ image,
                  const float* __restrict__ unary,
                  const float* __restrict__ theta,
                  const float* __restrict__ weight,
                  float* __restrict__ pout)
{
    int idx = blockIdx.x * 256 + threadIdx.x;
    if (idx >= NPIX) return;
    int w = idx & (WW - 1);
    int h = (idx >> 9) & (HH - 1);
    int b = idx >> 18;

    float t0 = theta[0], t1 = theta[1], t2 = theta[2];
    const float* img = image + b * HW;
    const float* un  = unary + b * HW;
    float c = img[h * WW + w] * 255.0f;

    float A[9];
    float msg = 0.0f;
#pragma unroll
    for (int k = 0; k < 9; k++) {
        int dx = k / 3 - 1, dy = k % 3 - 1;
        int hh = h + dx, ww = w + dy;
        float e = 0.0f;
        bool ok = (unsigned)hh < HH && (unsigned)ww < WW;
        if (ok) {
            float d    = img[hh * WW + ww] * 255.0f - c;
            float dist = t0 * (float)(dx * dx) + t1 * (float)(dy * dy) + t2 * d * d;
            e = __expf(-0.5f * dist);
        }
        A[k] = __expf(e);          // invalid neighbor -> exp(0) = 1
        if (ok) msg += A[k] * un[hh * WW + ww];   // iter-1 message (pred=unary)
    }

    // Sum S from fp16-ROUNDED values: exactly what the message pass reads
    // (forward at p and backward at p-d are bit-identical by symmetry).
    float S = AC;
#pragma unroll
    for (int k = 0; k < 9; k++)
        if (k != 4) S += __half2float(__float2half(A[k]));
    float invSw = 0.5f * weight[0] / S;

    int pidx = b * IMG + FPAD + h * RSTR + w;
    g_A[0][pidx] = __float2half(A[5]);   // (0, 1)
    g_A[1][pidx] = __float2half(A[6]);   // (1,-1)
    g_A[2][pidx] = __float2half(A[7]);   // (1, 0)
    g_A[3][pidx] = __float2half(A[8]);   // (1, 1)
    g_invS[idx]  = __float2half(invSw);

    // iteration 1 output (padded)
    pout[pidx] = 0.5f * un[h * WW + w] + invSw * msg;
}

__device__ __forceinline__ float2 h2f(const u32 u) {
    return __half22float2(*reinterpret_cast<const __half2*>(&u));
}
__device__ __forceinline__ void unpack8(const uint4 v, float* f) {
    float2 a = h2f(v.x), b = h2f(v.y), c = h2f(v.z), d = h2f(v.w);
    f[0] = a.x; f[1] = a.y; f[2] = b.x; f[3] = b.y;
    f[4] = c.x; f[5] = c.y; f[6] = d.x; f[7] = d.y;
}

// ---------------------------------------------------------------------------
// One Jacobi update of 8 px at (b, gh, cols c..c+7). pred read via pc
// (element at (gh, c)) with row stride ps — padded global (ps=RSTR) or smem
// strip with zero guards (ps=SMS). A/invS/unary from global (unconditional).
// ---------------------------------------------------------------------------
__device__ __forceinline__ void jacobi8(
    int b, int gh, int c,
    const float* __restrict__ pc, int ps,
    const float* __restrict__ unary, float* o)
{
    int uidx = b * HW + (gh << 9) + c;
    int pidx = b * IMG + FPAD + gh * RSTR + c;
    int up   = pidx - RSTR;

    const __half* P0 = g_A[0]; const __half* P1 = g_A[1];
    const __half* P2 = g_A[2]; const __half* P3 = g_A[3];
    uint4 F0 = __ldg((const uint4*)&P0[pidx]);
    uint4 F1 = __ldg((const uint4*)&P1[pidx]);
    uint4 F2 = __ldg((const uint4*)&P2[pidx]);
    uint4 F3 = __ldg((const uint4*)&P3[pidx]);
    u32   B0 = __ldg((const u32*)&P0[pidx - 2]);  // .y = A0[p-1]
    uint4 U1 = __ldg((const uint4*)&P1[up]);
    u32   E1 = __ldg((const u32*)&P1[up + 8]);    // .x = A1[u+8]
    uint4 U2 = __ldg((const uint4*)&P2[up]);
    uint4 U3 = __ldg((const uint4*)&P3[up]);
    u32   E3 = __ldg((const u32*)&P3[up - 2]);    // .y = A3[u-1]
    uint4 SV = __ldg((const uint4*)&g_invS[uidx]);
    float4 ua = __ldg((const float4*)(unary + uidx));
    float4 ub = __ldg((const float4*)(unary + uidx + 4));

    float row[3][10];
#pragma unroll
    for (int r = 0; r < 3; r++) {
        const float* p = pc + (r - 1) * ps;
        float4 v0 = *(const float4*)p;
        float4 v1 = *(const float4*)(p + 4);
        row[r][1] = v0.x; row[r][2] = v0.y; row[r][3] = v0.z; row[r][4] = v0.w;
        row[r][5] = v1.x; row[r][6] = v1.y; row[r][7] = v1.z; row[r][8] = v1.w;
        row[r][0] = p[-1];
        row[r][9] = p[8];
    }

    float acc[8];
#pragma unroll
    for (int j = 0; j < 8; j++) acc[j] = AC * row[1][j + 1];

    {   // dir0 (0,±1)
        float f[8]; unpack8(F0, f);
#pragma unroll
        for (int j = 0; j < 8; j++) acc[j] += f[j] * row[1][j + 2];
        acc[0] += h2f(B0).y * row[1][0];
#pragma unroll
        for (int j = 1; j < 8; j++) acc[j] += f[j - 1] * row[1][j];
    }
    {   // dir1 (+1,-1) fwd / (-1,+1) bwd
        float f[8]; unpack8(F1, f);
#pragma unroll
        for (int j = 0; j < 8; j++) acc[j] += f[j] * row[2][j];
        float u[8]; unpack8(U1, u);
#pragma unroll
        for (int j = 0; j < 7; j++) acc[j] += u[j + 1] * row[0][j + 2];
        acc[7] += h2f(E1).x * row[0][9];
    }
    {   // dir2 (+1,0) fwd / (-1,0) bwd
        float f[8]; unpack8(F2, f);
#pragma unroll
        for (int j = 0; j < 8; j++) acc[j] += f[j] * row[2][j + 1];
        float u[8]; unpack8(U2, u);
#pragma unroll
        for (int j = 0; j < 8; j++) acc[j] += u[j] * row[0][j + 1];
    }
    {   // dir3 (+1,+1) fwd / (-1,-1) bwd
        float f[8]; unpack8(F3, f);
#pragma unroll
        for (int j = 0; j < 8; j++) acc[j] += f[j] * row[2][j + 2];
        float u[8]; unpack8(U3, u);
        acc[0] += h2f(E3).y * row[0][0];
#pragma unroll
        for (int j = 1; j < 8; j++) acc[j] += u[j - 1] * row[0][j];
    }

    float s[8]; unpack8(SV, s);
    float un[8] = {ua.x, ua.y, ua.z, ua.w, ub.x, ub.y, ub.z, ub.w};
#pragma unroll
    for (int j = 0; j < 8; j++) o[j] = 0.5f * un[j] + s[j] * acc[j];
}

// ---------------------------------------------------------------------------
// Fused 3 Jacobi iterations on a 16-row x 512-col strip.
// bufA: 20 rows (R-2..R+17), bufB: 18 rows (R-1..R+16), stride SMS, with
// zero guard columns at idx 3 and 516. OOB-image rows stored as 0.
// All smem stores are vectorized (STS.128 x2 per octet).
// ---------------------------------------------------------------------------
__global__ __launch_bounds__(512, 2)
void fused3(const float* __restrict__ pin,
            const float* __restrict__ unary,
            float* __restrict__ pout, int last)
{
    extern __shared__ float sm[];
    float* bufA = sm;                  // 20 x SMS
    float* bufB = sm + 20 * SMS;       // 18 x SMS

    int tid = threadIdx.x;
    int blk = blockIdx.x;
    int b   = blk >> 5;
    int R   = (blk & 31) << 4;

    if (tid < 20)      { bufA[tid * SMS + 3] = 0.f; bufA[tid * SMS + 516] = 0.f; }
    else if (tid < 38) { int i = tid - 20;
                         bufB[i * SMS + 3] = 0.f; bufB[i * SMS + 516] = 0.f; }

    // phase 1: rows R-2..R+17 from global pin (padded, branch-free core)
    for (int oct = tid; oct < 20 * 64; oct += 512) {
        int i = oct >> 6, c = (oct & 63) << 3;
        int gh = R - 2 + i;
        float* dst = &bufA[i * SMS + 4 + c];
        if ((unsigned)gh < HH) {
            float o[8];
            const float* pc = pin + b * IMG + FPAD + gh * RSTR + c;
            jacobi8(b, gh, c, pc, RSTR, unary, o);
            *(float4*)dst       = make_float4(o[0], o[1], o[2], o[3]);
            *(float4*)(dst + 4) = make_float4(o[4], o[5], o[6], o[7]);
        } else {
            *(float4*)dst       = make_float4(0.f, 0.f, 0.f, 0.f);
            *(float4*)(dst + 4) = make_float4(0.f, 0.f, 0.f, 0.f);
        }
    }
    __syncthreads();

    // phase 2: rows R-1..R+16 from bufA
    for (int oct = tid; oct < 18 * 64; oct += 512) {
        int i = oct >> 6, c = (oct & 63) << 3;
        int gh = R - 1 + i;
        float* dst = &bufB[i * SMS + 4 + c];
        if ((unsigned)gh < HH) {
            float o[8];
            const float* pc = &bufA[(i + 1) * SMS + 4 + c];
            jacobi8(b, gh, c, pc, SMS, unary, o);
            *(float4*)dst       = make_float4(o[0], o[1], o[2], o[3]);
            *(float4*)(dst + 4) = make_float4(o[4], o[5], o[6], o[7]);
        } else {
            *(float4*)dst       = make_float4(0.f, 0.f, 0.f, 0.f);
            *(float4*)(dst + 4) = make_float4(0.f, 0.f, 0.f, 0.f);
        }
    }
    __syncthreads();

    // phase 3: rows R..R+15 from bufB, write global
    for (int oct = tid; oct < 16 * 64; oct += 512) {
        int i = oct >> 6, c = (oct & 63) << 3;
        int gh = R + i;
        float o[8];
        const float* pc = &bufB[(i + 1) * SMS + 4 + c];
        jacobi8(b, gh, c, pc, SMS, unary, o);
        float4 o0 = make_float4(o[0], o[1], o[2], o[3]);
        float4 o1 = make_float4(o[4], o[5], o[6], o[7]);
        if (last) {
            int uidx = b * HW + (gh << 9) + c;
            *(float4*)(pout + uidx)     = o0;
            *(float4*)(pout + uidx + 4) = o1;
        } else {
            int pidx = b * IMG + FPAD + gh * RSTR + c;
            *(float4*)(pout + pidx)     = o0;
            *(float4*)(pout + pidx + 4) = o1;
        }
    }
}

extern "C" void kernel_launch(void* const* d_in, const int* in_sizes, int n_in,
                              void* d_out, int out_size)
{
    const float* image  = (const float*)d_in[0];
    const float* unary  = (const float*)d_in[1];
    const float* theta  = (const float*)d_in[2];
    const float* weight = (const float*)d_in[3];
    float* out = (float*)d_out;

    void* baddr = nullptr;
    cudaGetSymbolAddress(&baddr, g_buf);   // non-stream API: capture-safe
    float* buf0 = (float*)baddr;
    float* buf1 = buf0 + PTOT;

    const int SMEM = (20 + 18) * SMS * (int)sizeof(float);   // 79,040 B
    cudaFuncSetAttribute(fused3, cudaFuncAttributeMaxDynamicSharedMemorySize, SMEM);

    build_kernel<<<NPIX / 256, 256>>>(image, unary, theta, weight, buf0);  // +iter 1
    fused3<<<BB * 32, 512, SMEM>>>(buf0, unary, buf1, 0);        // iters 2-4
    fused3<<<BB * 32, 512, SMEM>>>(buf1, unary, buf0, 0);        // iters 5-7
    fused3<<<BB * 32, 512, SMEM>>>(buf0, unary, out, 1);         // iters 8-10
}

// round 13
// speedup vs baseline: 1.1011x; 1.0434x over previous
#include <cuda_runtime.h>
#include <cuda_fp16.h>
#include <cstdint>

#define BB    16
#define HH    512
#define WW    512
#define HW    (HH * WW)
#define NPIX  (BB * HW)

#define RSTR  520                       // padded row stride
#define FPAD  528                       // per-image front pad
#define BPAD  528                       // per-image back pad
#define IMG   (FPAD + HH * RSTR + BPAD)
#define PTOT  (BB * IMG)

#define SMS   520                       // smem strip row stride (floats)

typedef unsigned int u32;

// A planes: padded; pads/gaps initialized to 1.0 (OOB softmax entry = exp(0)=1,
// so inline-S sums are exact at boundaries). Message terms at OOB multiply by
// pred=0 (g_buf pads stay zero-initialized, never written).
// Dirs: 0=(0,1) 1=(1,-1) 2=(1,0) 3=(1,1);  A = exp(entry), symmetric:
// A_d(p) == A_{-d}(p+d); center entry = exp(1).
__device__ __half g_A[4][PTOT];    // 34.2 MB
__device__ float  g_buf[2][PTOT];  // padded ping-pong pred buffers

#define AC 2.7182818284590452f     // exp(1): center softmax-numerator

// ---------------------------------------------------------------------------
__device__ __forceinline__ float2 h2f(const u32 u) {
    return __half22float2(*reinterpret_cast<const __half2*>(&u));
}
__device__ __forceinline__ u32 pack2(float a, float b) {
    __half2 h = __halves2half2(__float2half(a), __float2half(b));
    return *reinterpret_cast<u32*>(&h);
}
__device__ __forceinline__ void unpack8(const uint4 v, float* f) {
    float2 a = h2f(v.x), b = h2f(v.y), c = h2f(v.z), d = h2f(v.w);
    f[0] = a.x; f[1] = a.y; f[2] = b.x; f[3] = b.y;
    f[4] = c.x; f[5] = c.y; f[6] = d.x; f[7] = d.y;
}
// r[0..9] = p[-1..8]   (only for pointers where p[-1]/p[8] are in-bounds!)
__device__ __forceinline__ void ldrow(const float* p, float* r) {
    float4 v0 = *(const float4*)p;
    float4 v1 = *(const float4*)(p + 4);
    r[0] = p[-1];
    r[1] = v0.x; r[2] = v0.y; r[3] = v0.z; r[4] = v0.w;
    r[5] = v1.x; r[6] = v1.y; r[7] = v1.z; r[8] = v1.w;
    r[9] = p[8];
}
// guarded variant for UNPADDED arrays: edge scalars zeroed at image borders
__device__ __forceinline__ void ldrow_g(const float* p, float* r, int w8) {
    float4 v0 = *(const float4*)p;
    float4 v1 = *(const float4*)(p + 4);
    r[0] = (w8 > 0)      ? p[-1] : 0.0f;
    r[1] = v0.x; r[2] = v0.y; r[3] = v0.z; r[4] = v0.w;
    r[5] = v1.x; r[6] = v1.y; r[7] = v1.z; r[8] = v1.w;
    r[9] = (w8 + 8 < WW) ? p[8]  : 0.0f;
}
__device__ __forceinline__ void st8(float* d, const float* o) {
    *(float4*)d       = make_float4(o[0], o[1], o[2], o[3]);
    *(float4*)(d + 4) = make_float4(o[4], o[5], o[6], o[7]);
}
__device__ __forceinline__ void stz8(float* d) {
    *(float4*)d       = make_float4(0.f, 0.f, 0.f, 0.f);
    *(float4*)(d + 4) = make_float4(0.f, 0.f, 0.f, 0.f);
}

// ---------------------------------------------------------------------------
// Set A pads/gaps (front pad, per-row 8-elem gaps, back pad) to 1.0.
// ---------------------------------------------------------------------------
#define PADN (FPAD + HH * 8 + BPAD)     // 5152 pad elems per image
__global__ __launch_bounds__(256)
void init_pads()
{
    int e = blockIdx.x * 256 + threadIdx.x;
    if (e >= BB * PADN) return;
    int b = e / PADN, j = e - b * PADN;
    int off;
    if (j < FPAD)             off = j;
    else if (j < FPAD + HH*8) { int g = j - FPAD; off = FPAD + (g >> 3) * RSTR + WW + (g & 7); }
    else                      off = FPAD + HH * RSTR + (j - (FPAD + HH * 8));
    const __half one = __float2half(1.0f);
    int idx = b * IMG + off;
    g_A[0][idx] = one; g_A[1][idx] = one; g_A[2][idx] = one; g_A[3][idx] = one;
}

// ---------------------------------------------------------------------------
// Build pass + iteration 1, octet-per-thread, vectorized windows.
// ---------------------------------------------------------------------------
__global__ __launch_bounds__(256)
void build_kernel(const float* __restrict__ image,
                  const float* __restrict__ unary,
                  const float* __restrict__ theta,
                  const float* __restrict__ weight,
                  float* __restrict__ pout)
{
    int t  = blockIdx.x * 256 + threadIdx.x;
    int w8 = (t & 63) << 3;
    int h  = (t >> 6) & (HH - 1);
    int b  = t >> 15;
    int uidx = b * HW + (h << 9) + w8;

    float t0 = theta[0], t1 = theta[1], t2 = theta[2];
    float hw = 0.5f * weight[0];

    float win[3][10], uwin[3][10];
    bool rowok[3];
#pragma unroll
    for (int r = 0; r < 3; r++) {
        int gh = h + r - 1;
        rowok[r] = (unsigned)gh < HH;
        if (!rowok[r]) {
#pragma unroll
            for (int c = 0; c < 10; c++) { win[r][c] = 0.f; uwin[r][c] = 0.f; }
        } else {
            ldrow_g(image + uidx + (r - 1) * WW, win[r],  w8);
            ldrow_g(unary + uidx + (r - 1) * WW, uwin[r], w8);
        }
    }

    float geo[9];
#pragma unroll
    for (int k = 0; k < 9; k++) {
        int dx = k / 3 - 1, dy = k % 3 - 1;
        geo[k] = t0 * (float)(dx * dx) + t1 * (float)(dy * dy);
    }

    float A5[8], A6[8], A7[8], A8[8], outv[8];
#pragma unroll
    for (int j = 0; j < 8; j++) {
        float cc = win[1][j + 1] * 255.f;
        float S = AC, msg = 0.f;
#pragma unroll
        for (int k = 0; k < 9; k++) {
            int dx = k / 3 - 1, dy = k % 3 - 1;
            bool ok = rowok[1 + dx];
            if (dy < 0) ok = ok && (w8 + j > 0);
            if (dy > 0) ok = ok && (w8 + j + 1 < WW);
            float nb = win[1 + dx][j + 1 + dy];
            float d  = nb * 255.f - cc;
            float e  = ok ? __expf(-0.5f * (geo[k] + t2 * d * d)) : 0.f;
            float Af = __expf(e);
            if (k != 4) S += __half2float(__float2half(Af));
            msg += Af * uwin[1 + dx][j + 1 + dy];   // OOB: 1 * 0 = 0
            if (k == 5) A5[j] = Af;
            if (k == 6) A6[j] = Af;
            if (k == 7) A7[j] = Af;
            if (k == 8) A8[j] = Af;
        }
        outv[j] = 0.5f * uwin[1][j + 1] + __fdividef(hw, S) * msg;
    }

    int pidx = b * IMG + FPAD + h * RSTR + w8;
    uint4 v;
    v.x = pack2(A5[0], A5[1]); v.y = pack2(A5[2], A5[3]);
    v.z = pack2(A5[4], A5[5]); v.w = pack2(A5[6], A5[7]);
    *(uint4*)&g_A[0][pidx] = v;
    v.x = pack2(A6[0], A6[1]); v.y = pack2(A6[2], A6[3]);
    v.z = pack2(A6[4], A6[5]); v.w = pack2(A6[6], A6[7]);
    *(uint4*)&g_A[1][pidx] = v;
    v.x = pack2(A7[0], A7[1]); v.y = pack2(A7[2], A7[3]);
    v.z = pack2(A7[4], A7[5]); v.w = pack2(A7[6], A7[7]);
    *(uint4*)&g_A[2][pidx] = v;
    v.x = pack2(A8[0], A8[1]); v.y = pack2(A8[2], A8[3]);
    v.z = pack2(A8[4], A8[5]); v.w = pack2(A8[6], A8[7]);
    *(uint4*)&g_A[3][pidx] = v;
    st8(pout + pidx, outv);
}

// ---------------------------------------------------------------------------
// Two adjacent Jacobi rows (gh, gh+1) x 8 cols. A loads shared: up-row of
// gh+1 == forward row of gh. S computed inline from the loaded fp16 values.
// p0..p3: pred rows gh-1..gh+2, each pointing at col c (p[-1],p[8] valid).
// ---------------------------------------------------------------------------
__device__ __forceinline__ void jac2(
    int pidxA, int uidx,
    const float* p0, const float* p1, const float* p2, const float* p3,
    const float* __restrict__ unary, float hw, float* oA, float* oB)
{
    const __half* P0 = g_A[0]; const __half* P1 = g_A[1];
    const __half* P2 = g_A[2]; const __half* P3 = g_A[3];
    int pidxB = pidxA + RSTR, up = pidxA - RSTR;

    uint4 U1v = __ldg((const uint4*)&P1[up]);
    uint4 U2v = __ldg((const uint4*)&P2[up]);
    uint4 U3v = __ldg((const uint4*)&P3[up]);
    u32 E1u = __ldg((const u32*)&P1[up + 8]);
    u32 E3u = __ldg((const u32*)&P3[up - 2]);
    uint4 F0a = __ldg((const uint4*)&P0[pidxA]);
    uint4 F1a = __ldg((const uint4*)&P1[pidxA]);
    uint4 F2a = __ldg((const uint4*)&P2[pidxA]);
    uint4 F3a = __ldg((const uint4*)&P3[pidxA]);
    u32 B0a = __ldg((const u32*)&P0[pidxA - 2]);
    u32 E1a = __ldg((const u32*)&P1[pidxA + 8]);
    u32 E3a = __ldg((const u32*)&P3[pidxA - 2]);
    uint4 F0b = __ldg((const uint4*)&P0[pidxB]);
    uint4 F1b = __ldg((const uint4*)&P1[pidxB]);
    uint4 F2b = __ldg((const uint4*)&P2[pidxB]);
    uint4 F3b = __ldg((const uint4*)&P3[pidxB]);
    u32 B0b = __ldg((const u32*)&P0[pidxB - 2]);
    float4 ua0 = __ldg((const float4*)(unary + uidx));
    float4 ua1 = __ldg((const float4*)(unary + uidx + 4));
    float4 ub0 = __ldg((const float4*)(unary + uidx + WW));
    float4 ub1 = __ldg((const float4*)(unary + uidx + WW + 4));

    float SA[8], SB[8], accA[8], accB[8];

    // step 1: pred row gh-1 -> row gh backward terms (dirs 1,2,3)
    {
        float r[10]; ldrow(p0, r);
        float u1[8], u2[8], u3[8];
        unpack8(U1v, u1); unpack8(U2v, u2); unpack8(U3v, u3);
        float e1 = h2f(E1u).x, e3 = h2f(E3u).y;
#pragma unroll
        for (int j = 0; j < 8; j++) {
            float b1 = (j < 7) ? u1[j + 1] : e1;
            float b3 = (j > 0) ? u3[j - 1] : e3;
            accA[j] = b1 * r[j + 2] + u2[j] * r[j + 1] + b3 * r[j];
            SA[j]   = b1 + u2[j] + b3;
        }
    }
    // step 2: pred row gh -> row gh center+dir0; row gh+1 backward terms
    float f1a[8], f2a[8], f3a[8];
    unpack8(F1a, f1a); unpack8(F2a, f2a); unpack8(F3a, f3a);
    {
        float r[10]; ldrow(p1, r);
        float f0[8]; unpack8(F0a, f0);
        float b0a = h2f(B0a).y;
        float e1a = h2f(E1a).x, e3a = h2f(E3a).y;
#pragma unroll
        for (int j = 0; j < 8; j++) {
            float bw0 = (j > 0) ? f0[j - 1] : b0a;
            accA[j] += AC * r[j + 1] + f0[j] * r[j + 2] + bw0 * r[j];
            SA[j]   += f0[j] + bw0;
            float b1 = (j < 7) ? f1a[j + 1] : e1a;
            float b3 = (j > 0) ? f3a[j - 1] : e3a;
            accB[j] = b1 * r[j + 2] + f2a[j] * r[j + 1] + b3 * r[j];
            SB[j]   = b1 + f2a[j] + b3;
        }
    }
    // step 3: pred row gh+1 -> row gh forward terms; row gh+1 center+dir0
    {
        float r[10]; ldrow(p2, r);
        float f0[8]; unpack8(F0b, f0);
        float b0b = h2f(B0b).y;
#pragma unroll
        for (int j = 0; j < 8; j++) {
            accA[j] += f1a[j] * r[j] + f2a[j] * r[j + 1] + f3a[j] * r[j + 2];
            SA[j]   += f1a[j] + f2a[j] + f3a[j];
            float bw0 = (j > 0) ? f0[j - 1] : b0b;
            accB[j] += AC * r[j + 1] + f0[j] * r[j + 2] + bw0 * r[j];
            SB[j]   += f0[j] + bw0;
        }
    }
    // step 4: pred row gh+2 -> row gh+1 forward terms
    {
        float r[10]; ldrow(p3, r);
        float f1[8], f2[8], f3[8];
        unpack8(F1b, f1); unpack8(F2b, f2); unpack8(F3b, f3);
#pragma unroll
        for (int j = 0; j < 8; j++) {
            accB[j] += f1[j] * r[j] + f2[j] * r[j + 1] + f3[j] * r[j + 2];
            SB[j]   += f1[j] + f2[j] + f3[j];
        }
    }

    float unA[8] = {ua0.x, ua0.y, ua0.z, ua0.w, ua1.x, ua1.y, ua1.z, ua1.w};
    float unB[8] = {ub0.x, ub0.y, ub0.z, ub0.w, ub1.x, ub1.y, ub1.z, ub1.w};
#pragma unroll
    for (int j = 0; j < 8; j++) {
        oA[j] = 0.5f * unA[j] + __fdividef(hw, AC + SA[j]) * accA[j];
        oB[j] = 0.5f * unB[j] + __fdividef(hw, AC + SB[j]) * accB[j];
    }
}

// ---------------------------------------------------------------------------
// Fused 3 iterations on a 16-row x 512-col strip, 2-row groups.
// bufA rows R-2..R+17 (20), bufB rows R-1..R+16 (18); guards at cols 3/516.
// ---------------------------------------------------------------------------
__global__ __launch_bounds__(512)
void fused3(const float* __restrict__ pin,
            const float* __restrict__ unary,
            const float* __restrict__ weight,
            float* __restrict__ pout, int last)
{
    extern __shared__ float sm[];
    float* bufA = sm;                  // 20 x SMS
    float* bufB = sm + 20 * SMS;       // 18 x SMS

    int tid = threadIdx.x;
    int blk = blockIdx.x;
    int b   = blk >> 5;
    int R   = (blk & 31) << 4;
    float hw = 0.5f * __ldg(weight);

    if (tid < 20)      { bufA[tid * SMS + 3] = 0.f; bufA[tid * SMS + 516] = 0.f; }
    else if (tid < 38) { int i = tid - 20;
                         bufB[i * SMS + 3] = 0.f; bufB[i * SMS + 516] = 0.f; }

    // phase 1: rows R-2..R+17 (10 groups x 64 cols) from global -> bufA
    for (int g = tid; g < 640; g += 512) {
        int gi = g >> 6, c = (g & 63) << 3;
        int gh = R - 2 + gi * 2;
        float* dA0 = &bufA[(gi * 2) * SMS + 4 + c];
        if ((unsigned)gh < HH) {
            int pidxA = b * IMG + FPAD + gh * RSTR + c;
            int uidx  = b * HW + (gh << 9) + c;
            const float* pb = pin + pidxA;
            float oA[8], oB[8];
            jac2(pidxA, uidx, pb - RSTR, pb, pb + RSTR, pb + 2 * RSTR,
                 unary, hw, oA, oB);
            st8(dA0, oA); st8(dA0 + SMS, oB);
        } else { stz8(dA0); stz8(dA0 + SMS); }
    }
    __syncthreads();

    // phase 2: 10 groups covering rows R-2..R+17; keep rows R-1..R+16 -> bufB
    for (int g = tid; g < 640; g += 512) {
        int gi = g >> 6, c = (g & 63) << 3;
        int gh = R - 2 + gi * 2;
        int jB0 = 2 * gi - 1, jB1 = 2 * gi;
        bool w0 = (gi > 0), w1 = (gi < 9);
        if ((unsigned)gh < HH) {
            int pidxA = b * IMG + FPAD + gh * RSTR + c;
            int uidx  = b * HW + (gh << 9) + c;
            int iA = 2 * gi;
            const float* q0 = &bufA[(iA > 0 ? iA - 1 : 0) * SMS + 4 + c];
            const float* q1 = &bufA[iA * SMS + 4 + c];
            const float* q2 = &bufA[(iA + 1) * SMS + 4 + c];
            const float* q3 = &bufA[(iA + 2 < 20 ? iA + 2 : 19) * SMS + 4 + c];
            float oA[8], oB[8];
            jac2(pidxA, uidx, q0, q1, q2, q3, unary, hw, oA, oB);
            if (w0) st8(&bufB[jB0 * SMS + 4 + c], oA);
            if (w1) st8(&bufB[jB1 * SMS + 4 + c], oB);
        } else {
            if (w0) stz8(&bufB[jB0 * SMS + 4 + c]);
            if (w1) stz8(&bufB[jB1 * SMS + 4 + c]);
        }
    }
    __syncthreads();

    // phase 3: rows R..R+15 (8 groups x 64 cols, exactly 512 items) -> global
    {
        int g = tid;
        int gi = g >> 6, c = (g & 63) << 3;
        int gh = R + 2 * gi;
        int pidxA = b * IMG + FPAD + gh * RSTR + c;
        int uidx  = b * HW + (gh << 9) + c;
        int iB = 2 * gi + 1;
        const float* q0 = &bufB[(iB - 1) * SMS + 4 + c];
        const float* q1 = &bufB[iB * SMS + 4 + c];
        const float* q2 = &bufB[(iB + 1) * SMS + 4 + c];
        const float* q3 = &bufB[(iB + 2) * SMS + 4 + c];
        float oA[8], oB[8];
        jac2(pidxA, uidx, q0, q1, q2, q3, unary, hw, oA, oB);
        if (last) {
            st8(pout + uidx, oA);
            st8(pout + uidx + WW, oB);
        } else {
            st8(pout + pidxA, oA);
            st8(pout + pidxA + RSTR, oB);
        }
    }
}

extern "C" void kernel_launch(void* const* d_in, const int* in_sizes, int n_in,
                              void* d_out, int out_size)
{
    const float* image  = (const float*)d_in[0];
    const float* unary  = (const float*)d_in[1];
    const float* theta  = (const float*)d_in[2];
    const float* weight = (const float*)d_in[3];
    float* out = (float*)d_out;

    void* baddr = nullptr;
    cudaGetSymbolAddress(&baddr, g_buf);   // non-stream API: capture-safe
    float* buf0 = (float*)baddr;
    float* buf1 = buf0 + PTOT;

    const int SMEM = (20 + 18) * SMS * (int)sizeof(float);   // 79,040 B
    cudaFuncSetAttribute(fused3, cudaFuncAttributeMaxDynamicSharedMemorySize, SMEM);

    init_pads<<<(BB * PADN + 255) / 256, 256>>>();
    build_kernel<<<(NPIX / 8) / 256, 256>>>(image, unary, theta, weight, buf0); // +iter1
    fused3<<<BB * 32, 512, SMEM>>>(buf0, unary, weight, buf1, 0);   // iters 2-4
    fused3<<<BB * 32, 512, SMEM>>>(buf1, unary, weight, buf0, 0);   // iters 5-7
    fused3<<<BB * 32, 512, SMEM>>>(buf0, unary, weight, out, 1);    // iters 8-10
}